// round 1
// baseline (speedup 1.0000x reference)
#include <cuda_runtime.h>

#define T_STEPS 16384
#define X_DIM   512
#define H_DIM   1024
#define NBLK    128
#define ROWS_PER_BLK (H_DIM / NBLK)    // 8 rows per block
#define NTHREADS (ROWS_PER_BLK * 32)   // 256 threads, 1 warp per row

// Per-step arrival counters. Zeroed by cudaMemsetAsync at every launch so the
// kernel is graph-replay safe (no runtime allocation).
__device__ unsigned int g_cnt[T_STEPS];

__global__ void __launch_bounds__(NTHREADS, 1)
rnn_scan_kernel(const float* __restrict__ x_seq,
                const float* __restrict__ h0,
                const float* __restrict__ A_raw,
                const float* __restrict__ B,
                const float* __restrict__ c,
                float* __restrict__ out)
{
    const int warp = threadIdx.x >> 5;
    const int lane = threadIdx.x & 31;
    const int row  = blockIdx.x * ROWS_PER_BLK + warp;

    __shared__ float Bs[ROWS_PER_BLK][X_DIM];   // 16 KB

    // ---- Prologue: fold A = 0.9 I + 0.1 A_raw into registers.
    // Lane l of warp w holds A[row][l + 32k], k = 0..31.
    float a[32];
#pragma unroll
    for (int k = 0; k < 32; ++k) {
        int j = lane + 32 * k;
        float v = 0.1f * A_raw[(size_t)row * H_DIM + j];
        if (j == row) v += 0.9f;
        a[k] = v;
    }
    // B rows for this block -> smem (coalesced).
    for (int i = threadIdx.x; i < ROWS_PER_BLK * X_DIM; i += NTHREADS) {
        int rr = i / X_DIM, jj = i % X_DIM;
        Bs[rr][jj] = B[((size_t)blockIdx.x * ROWS_PER_BLK + rr) * X_DIM + jj];
    }
    const float c_r = (lane == 0) ? c[row] : 0.0f;   // fold bias into lane 0 partial
    __syncthreads();

    for (int t = 0; t < T_STEPS; ++t) {
        // ---- 1) Fused input projection: bx partial for this row.
        // Runs BEFORE the spin-wait, so it hides in otherwise-dead time.
        const float* xt = x_seq + (size_t)t * X_DIM;
        float xv[X_DIM / 32];
#pragma unroll
        for (int k = 0; k < X_DIM / 32; ++k) xv[k] = xt[lane + 32 * k];
        float b0 = 0.f, b1 = 0.f, b2 = 0.f, b3 = 0.f;
#pragma unroll
        for (int k = 0; k < X_DIM / 32; k += 4) {
            b0 += Bs[warp][lane + 32 * (k + 0)] * xv[k + 0];
            b1 += Bs[warp][lane + 32 * (k + 1)] * xv[k + 1];
            b2 += Bs[warp][lane + 32 * (k + 2)] * xv[k + 2];
            b3 += Bs[warp][lane + 32 * (k + 3)] * xv[k + 3];
        }
        float acc = ((b0 + b1) + (b2 + b3)) + c_r;

        // ---- 2) Wait for h_t to be fully published (all NBLK slices).
        const float* hsrc;
        if (t == 0) {
            hsrc = h0;
        } else {
            hsrc = out + (size_t)(t - 1) * H_DIM;
            unsigned v;
            do {
                asm volatile("ld.acquire.gpu.global.u32 %0, [%1];"
                             : "=r"(v) : "l"(g_cnt + (t - 1)) : "memory");
            } while (v != (unsigned)NBLK);
        }

        // ---- 3) A·h_t for this row: batched loads (MLP=32), 4 accumulators.
        float hv[32];
#pragma unroll
        for (int k = 0; k < 32; ++k) hv[k] = hsrc[lane + 32 * k];
        float s0 = 0.f, s1 = 0.f, s2 = 0.f, s3 = 0.f;
#pragma unroll
        for (int k = 0; k < 32; k += 4) {
            s0 += a[k + 0] * hv[k + 0];
            s1 += a[k + 1] * hv[k + 1];
            s2 += a[k + 2] * hv[k + 2];
            s3 += a[k + 3] * hv[k + 3];
        }
        acc += (s0 + s1) + (s2 + s3);

        // ---- 4) Warp reduce + tanh + publish this row of h_{t+1}.
#pragma unroll
        for (int off = 16; off; off >>= 1)
            acc += __shfl_xor_sync(0xffffffffu, acc, off);

        if (lane == 0) {
            out[(size_t)t * H_DIM + row] = tanhf(acc);
        }

        // ---- 5) Signal: make writes visible gpu-wide, then one arrival/block.
        __threadfence();
        __syncthreads();
        if (threadIdx.x == 0) {
            asm volatile("red.release.gpu.global.add.u32 [%0], %1;"
                         :: "l"(g_cnt + t), "r"(1u) : "memory");
        }
    }
}

extern "C" void kernel_launch(void* const* d_in, const int* in_sizes, int n_in,
                              void* d_out, int out_size)
{
    // metadata order: x_seq [T,X], h0 [H], A_raw [H,H], B [H,X], c [H]
    const float* x_seq = (const float*)d_in[0];
    const float* h0    = (const float*)d_in[1];
    const float* A_raw = (const float*)d_in[2];
    const float* B     = (const float*)d_in[3];
    const float* c     = (const float*)d_in[4];
    float* out = (float*)d_out;

    void* cnt_ptr = nullptr;
    cudaGetSymbolAddress(&cnt_ptr, g_cnt);
    cudaMemsetAsync(cnt_ptr, 0, T_STEPS * sizeof(unsigned int), 0);

    rnn_scan_kernel<<<NBLK, NTHREADS>>>(x_seq, h0, A_raw, B, c, out);
}